// round 1
// baseline (speedup 1.0000x reference)
#include <cuda_runtime.h>

// WOS filter: per (pixel, channel) weighted order statistic over 54 values.
// Fixed problem shape.
#define NCH   8
#define MD    54
#define BATCH 4
#define HH    160
#define WW    160
#define HO    158
#define WO    158
#define LPIX  (HO * WO)

__global__ __launch_bounds__(128) void WOS_72842645340328_kernel(
    const float* __restrict__ x,
    const float* __restrict__ weight,
    const float* __restrict__ bias,
    const float* __restrict__ mask,
    float* __restrict__ out,
    int total)
{
    int i = blockIdx.x * blockDim.x + threadIdx.x;
    if (i >= total) return;

    // out flat index i = n*NCH + c  (raw reinterpret in reference)
    int c  = i & 7;
    int n  = i >> 3;
    int b  = n / LPIX;
    int l  = n - b * LPIX;
    int ho = l / WO;
    int wo = l - ho * WO;

    const float* xb = x + ((b * 3) * HH + ho) * WW + wo;
    const float* mk = mask   + c * MD;
    const float* wt = weight + c * MD;

    float mx[MD];
    float w[MD];

    // Gather 3x3x3 patch; feature d = ch*9 + kh*3 + kw (torch Unfold order).
    // mx[d] = v + mask[d]; mx[27+d] = -v + mask[27+d]
#pragma unroll
    for (int ch = 0; ch < 3; ++ch)
#pragma unroll
        for (int kh = 0; kh < 3; ++kh)
#pragma unroll
            for (int kw = 0; kw < 3; ++kw) {
                float v = __ldg(xb + (ch * HH + kh) * WW + kw);
                int d = ch * 9 + kh * 3 + kw;
                mx[d]      = v + __ldg(mk + d);
                mx[27 + d] = __ldg(mk + 27 + d) - v;
            }

#pragma unroll
    for (int j = 0; j < MD; ++j) w[j] = __ldg(wt + j);

    float Bc = __ldg(bias + c);

    // answer = min{ mx_e : sum_j w_j*[mx_j >= mx_e] <= Bc }, else max(mx)
    float best = __int_as_float(0x7f800000);   // +inf
    float maxv = -best;

#pragma unroll
    for (int e = 0; e < MD; ++e) {
        float t = mx[e];
        float f0 = 0.f, f1 = 0.f;
#pragma unroll
        for (int j = 0; j < MD; j += 2) {
            if (mx[j]     >= t) f0 += w[j];
            if (mx[j + 1] >= t) f1 += w[j + 1];
        }
        float f = f0 + f1;
        maxv = fmaxf(maxv, t);
        if (f <= Bc) best = fminf(best, t);
    }

    out[i] = (best <= 3.0e38f) ? best : maxv;
}

extern "C" void kernel_launch(void* const* d_in, const int* in_sizes, int n_in,
                              void* d_out, int out_size)
{
    const float* x      = (const float*)d_in[0];
    const float* weight = (const float*)d_in[1];
    const float* bias   = (const float*)d_in[2];
    const float* mask   = (const float*)d_in[3];
    float* out = (float*)d_out;

    int total = out_size;  // 4*8*158*158 = 798848
    int threads = 128;
    int blocks = (total + threads - 1) / threads;
    WOS_72842645340328_kernel<<<blocks, threads>>>(x, weight, bias, mask, out, total);
}

// round 2
// speedup vs baseline: 1.3549x; 1.3549x over previous
#include <cuda_runtime.h>

// WOS filter: per (pixel, channel) weighted order statistic over 54 values.
// Diagonal-pair rank computation: each of the 1431 unordered pairs is compared
// once, updating both elements' rank-sums with complementary predicates.
#define NCH   8
#define MD    54
#define HH    160
#define WW    160
#define HO    158
#define WO    158
#define LPIX  (HO * WO)

__global__ __launch_bounds__(128, 2) void WOS_72842645340328_kernel(
    const float* __restrict__ x,
    const float* __restrict__ weight,
    const float* __restrict__ bias,
    const float* __restrict__ mask,
    float* __restrict__ out)
{
    int i = blockIdx.x * blockDim.x + threadIdx.x;

    // out flat index i = n*NCH + c  (raw reinterpret in reference)
    int c  = i & 7;
    int n  = i >> 3;
    int b  = n / LPIX;
    int l  = n - b * LPIX;
    int ho = l / WO;
    int wo = l - ho * WO;

    const float* xb = x + ((b * 3) * HH + ho) * WW + wo;
    const float* mk = mask   + c * MD;
    const float* wt = weight + c * MD;

    float mx[MD];
    float w[MD];

    // Gather 3x3x3 patch; feature d = ch*9 + kh*3 + kw (torch Unfold order).
    // mx[d] = v + mask[d]; mx[27+d] = mask[27+d] - v
#pragma unroll
    for (int ch = 0; ch < 3; ++ch)
#pragma unroll
        for (int kh = 0; kh < 3; ++kh)
#pragma unroll
            for (int kw = 0; kw < 3; ++kw) {
                float v = __ldg(xb + (ch * HH + kh) * WW + kw);
                int d = ch * 9 + kh * 3 + kw;
                mx[d]      = v + __ldg(mk + d);
                mx[27 + d] = __ldg(mk + 27 + d) - v;
            }

#pragma unroll
    for (int j = 0; j < MD; ++j) w[j] = __ldg(wt + j);

    float Bc = __ldg(bias + c);

    // f[e] = sum_j w[j] * [mx[j] >= mx[e]]  (self term: w[e])
    float f[MD];
#pragma unroll
    for (int e = 0; e < MD; ++e) f[e] = w[e];

#pragma unroll
    for (int e = 0; e < MD; ++e) {
#pragma unroll
        for (int j = e + 1; j < MD; ++j) {
            bool p = (mx[j] >= mx[e]);
            if (p)  f[e] += w[j];
            if (!p) f[j] += w[e];
        }
    }

    // answer = min{ mx_e : f[e] <= Bc }, else max(mx)
    float best = __int_as_float(0x7f800000);   // +inf
    float maxv = -best;

#pragma unroll
    for (int e = 0; e < MD; ++e) {
        maxv = fmaxf(maxv, mx[e]);
        if (f[e] <= Bc) best = fminf(best, mx[e]);
    }

    out[i] = (best <= 3.0e38f) ? best : maxv;
}

extern "C" void kernel_launch(void* const* d_in, const int* in_sizes, int n_in,
                              void* d_out, int out_size)
{
    const float* x      = (const float*)d_in[0];
    const float* weight = (const float*)d_in[1];
    const float* bias   = (const float*)d_in[2];
    const float* mask   = (const float*)d_in[3];
    float* out = (float*)d_out;

    // out_size = 4*8*158*158 = 798848 = 6241 * 128 exactly
    WOS_72842645340328_kernel<<<798848 / 128, 128>>>(x, weight, bias, mask, out);
}